// round 1
// baseline (speedup 1.0000x reference)
#include <cuda_runtime.h>
#include <math.h>

#define VV 3
#define CC 32
#define HH 128
#define WW 160
#define DD 128
#define HW (HH*WW)
#define CHW (CC*HW)
#define DHW ((long)DD*HW)
#define DCHUNK 16

// Precomputed per-src-view projection: p = A*[x,y,1]*depth + t, px = p.x/p.z - 0.5
__device__ float g_A[VV-1][9];
__device__ float g_t[VV-1][3];

__global__ void setup_kernel(const float* __restrict__ intr,
                             const float* __restrict__ extr)
{
    if (threadIdx.x != 0 || blockIdx.x != 0) return;

    // inverse of ref intrinsics (3x3, adjugate)
    float K[9];
    #pragma unroll
    for (int i = 0; i < 9; i++) K[i] = intr[i];
    float det = K[0]*(K[4]*K[8]-K[5]*K[7])
              - K[1]*(K[3]*K[8]-K[5]*K[6])
              + K[2]*(K[3]*K[7]-K[4]*K[6]);
    float id = 1.f/det;
    float iK[9];
    iK[0]=(K[4]*K[8]-K[5]*K[7])*id;
    iK[1]=(K[2]*K[7]-K[1]*K[8])*id;
    iK[2]=(K[1]*K[5]-K[2]*K[4])*id;
    iK[3]=(K[5]*K[6]-K[3]*K[8])*id;
    iK[4]=(K[0]*K[8]-K[2]*K[6])*id;
    iK[5]=(K[2]*K[3]-K[0]*K[5])*id;
    iK[6]=(K[3]*K[7]-K[4]*K[6])*id;
    iK[7]=(K[1]*K[6]-K[0]*K[7])*id;
    iK[8]=(K[0]*K[4]-K[1]*K[3])*id;

    // inverse of ref extrinsic (4x4, Gauss-Jordan w/ partial pivot)
    float M[4][8];
    for (int r = 0; r < 4; r++)
        for (int c = 0; c < 4; c++) {
            M[r][c]   = extr[r*4+c];
            M[r][4+c] = (r == c) ? 1.f : 0.f;
        }
    for (int col = 0; col < 4; col++) {
        int piv = col; float best = fabsf(M[col][col]);
        for (int r = col+1; r < 4; r++) {
            float a = fabsf(M[r][col]);
            if (a > best) { best = a; piv = r; }
        }
        if (piv != col)
            for (int c = 0; c < 8; c++) {
                float tmp = M[col][c]; M[col][c] = M[piv][c]; M[piv][c] = tmp;
            }
        float inv = 1.f/M[col][col];
        for (int c = 0; c < 8; c++) M[col][c] *= inv;
        for (int r = 0; r < 4; r++) {
            if (r == col) continue;
            float f = M[r][col];
            for (int c = 0; c < 8; c++) M[r][c] -= f*M[col][c];
        }
    }
    float iE0[16];
    for (int r = 0; r < 4; r++)
        for (int c = 0; c < 4; c++) iE0[r*4+c] = M[r][4+c];

    const float sx = (float)WW/(float)(WW-1);
    const float sy = (float)HH/(float)(HH-1);

    for (int v = 1; v < VV; v++) {
        const float* Ev = extr + v*16;
        float rel[3][4];
        for (int r = 0; r < 3; r++)
            for (int c = 0; c < 4; c++) {
                float s = 0.f;
                for (int k = 0; k < 4; k++) s += Ev[r*4+k]*iE0[k*4+c];
                rel[r][c] = s;
            }
        float A[3][3];
        for (int r = 0; r < 3; r++)
            for (int c = 0; c < 3; c++) {
                float s = 0.f;
                for (int k = 0; k < 3; k++) s += rel[r][k]*iK[k*3+c];
                A[r][c] = s;
            }
        float t0 = rel[0][3]*sx, t1 = rel[1][3]*sy, t2 = rel[2][3];
        for (int c = 0; c < 3; c++) { A[0][c] *= sx; A[1][c] *= sy; }

        float* gA = g_A[v-1]; float* gt = g_t[v-1];
        for (int r = 0; r < 3; r++)
            for (int c = 0; c < 3; c++) gA[r*3+c] = A[r][c];
        gt[0] = t0; gt[1] = t1; gt[2] = t2;
    }
}

// Bilinear sampling setup: weights (with validity folded) + clamped flat indices
struct Bilin {
    float w00, w01, w10, w11;
    int   i00, i01, i10, i11;
};

__device__ __forceinline__ Bilin bilin_setup(float px, float py)
{
    Bilin b;
    float x0f = floorf(px), y0f = floorf(py);
    float wx1 = px - x0f, wx0 = 1.f - wx1;
    float wy1 = py - y0f, wy0 = 1.f - wy1;
    float x1f = x0f + 1.f, y1f = y0f + 1.f;

    bool vx0 = (x0f >= 0.f) && (x0f <= (float)(WW-1));
    bool vx1 = (x1f >= 0.f) && (x1f <= (float)(WW-1));
    bool vy0 = (y0f >= 0.f) && (y0f <= (float)(HH-1));
    bool vy1 = (y1f >= 0.f) && (y1f <= (float)(HH-1));

    int ix0 = min(max((int)x0f, 0), WW-1);
    int ix1 = min(max((int)x1f, 0), WW-1);
    int iy0 = min(max((int)y0f, 0), HH-1);
    int iy1 = min(max((int)y1f, 0), HH-1);

    b.w00 = (vx0 && vy0) ? wx0*wy0 : 0.f;
    b.w01 = (vx1 && vy0) ? wx1*wy0 : 0.f;
    b.w10 = (vx0 && vy1) ? wx0*wy1 : 0.f;
    b.w11 = (vx1 && vy1) ? wx1*wy1 : 0.f;
    b.i00 = iy0*WW + ix0;
    b.i01 = iy0*WW + ix1;
    b.i10 = iy1*WW + ix0;
    b.i11 = iy1*WW + ix1;
    return b;
}

__global__ __launch_bounds__(WW)
void cost_volume_kernel(const float* __restrict__ feat,
                        const float* __restrict__ depths,
                        float* __restrict__ out)
{
    const int x  = threadIdx.x;
    const int y  = blockIdx.x;
    const int d0 = blockIdx.y * DCHUNK;
    const float fx = (float)x, fy = (float)y;

    // hoist ref feature values across all depths
    float refv[CC];
    const float* f0 = feat + y*WW + x;
    #pragma unroll
    for (int c = 0; c < CC; c++) refv[c] = __ldg(f0 + c*HW);

    // per-view rays (constant over depth)
    float A0[9], A1[9], t0v[3], t1v[3];
    #pragma unroll
    for (int i = 0; i < 9; i++) { A0[i] = g_A[0][i]; A1[i] = g_A[1][i]; }
    #pragma unroll
    for (int i = 0; i < 3; i++) { t0v[i] = g_t[0][i]; t1v[i] = g_t[1][i]; }

    const float r1x = A0[0]*fx + A0[1]*fy + A0[2];
    const float r1y = A0[3]*fx + A0[4]*fy + A0[5];
    const float r1z = A0[6]*fx + A0[7]*fy + A0[8];
    const float r2x = A1[0]*fx + A1[1]*fy + A1[2];
    const float r2y = A1[3]*fx + A1[4]*fy + A1[5];
    const float r2z = A1[6]*fx + A1[7]*fy + A1[8];

    const float* f1 = feat + CHW;
    const float* f2 = feat + 2*CHW;
    float* outp = out + y*WW + x;

    for (int dd = 0; dd < DCHUNK; dd++) {
        const int d = d0 + dd;
        const float depth = __ldg(depths + d);

        float iz1 = 1.f / (r1z*depth + t0v[2]);
        float px1 = (r1x*depth + t0v[0])*iz1 - 0.5f;
        float py1 = (r1y*depth + t0v[1])*iz1 - 0.5f;
        float iz2 = 1.f / (r2z*depth + t1v[2]);
        float px2 = (r2x*depth + t1v[0])*iz2 - 0.5f;
        float py2 = (r2y*depth + t1v[1])*iz2 - 0.5f;

        Bilin a = bilin_setup(px1, py1);
        Bilin bb = bilin_setup(px2, py2);

        float* outd = outp + (long)d * HW;

        #pragma unroll
        for (int c = 0; c < CC; c++) {
            const float* p1 = f1 + c*HW;
            const float* p2 = f2 + c*HW;
            float s1 = a.w00*__ldg(p1 + a.i00) + a.w01*__ldg(p1 + a.i01)
                     + a.w10*__ldg(p1 + a.i10) + a.w11*__ldg(p1 + a.i11);
            float s2 = bb.w00*__ldg(p2 + bb.i00) + bb.w01*__ldg(p2 + bb.i01)
                     + bb.w10*__ldg(p2 + bb.i10) + bb.w11*__ldg(p2 + bb.i11);
            float r  = refv[c];
            float sm = (r + s1 + s2) * (1.f/3.f);
            float sq = (r*r + s1*s1 + s2*s2) * (1.f/3.f);
            outd[(long)c * DHW] = sq - sm*sm;
        }
    }
}

extern "C" void kernel_launch(void* const* d_in, const int* in_sizes, int n_in,
                              void* d_out, int out_size)
{
    // Identify inputs by element count (all four sizes are distinct):
    // depth_values: 1*128 = 128
    // features_2d : 3*1*32*128*160 = 1966080
    // intrinsics  : 3*1*3*3 = 27
    // extrinsics  : 3*1*4*4 = 48
    const float* depths = nullptr;
    const float* feat   = nullptr;
    const float* intr   = nullptr;
    const float* extr   = nullptr;
    for (int i = 0; i < n_in; i++) {
        switch (in_sizes[i]) {
            case DD:            depths = (const float*)d_in[i]; break;
            case VV*CHW:        feat   = (const float*)d_in[i]; break;
            case VV*9:          intr   = (const float*)d_in[i]; break;
            case VV*16:         extr   = (const float*)d_in[i]; break;
            default: break;
        }
    }
    // fall back to declared order if anything went unmatched
    if (!depths) depths = (const float*)d_in[0];
    if (!feat)   feat   = (const float*)d_in[1];
    if (!intr)   intr   = (const float*)d_in[2];
    if (!extr)   extr   = (const float*)d_in[3];

    setup_kernel<<<1, 1>>>(intr, extr);

    dim3 grid(HH, DD / DCHUNK);
    cost_volume_kernel<<<grid, WW>>>(feat, depths, (float*)d_out);
}